// round 11
// baseline (speedup 1.0000x reference)
#include <cuda_runtime.h>
#include <cstddef>

#define C_DIM 64
#define K_DIM 64
#define P_DIM (256 * 256)        // H*W = 65536
#define RED_BLOCKS 256           // reduction blocks (256 pixels each)
#define CHUNKS_PER_REP 512       // 32 KB chunks
#define COPY_BLOCKS (K_DIM * CHUNKS_PER_REP)        // 32768
#define N4_PER_REP (C_DIM * P_DIM / 4)              // 1,048,576 float4 per replica
#define F4_PER_CHUNK (N4_PER_REP / CHUNKS_PER_REP)  // 2048 float4 = 32KB

// Global accumulators. Zero-initialized at load; the means kernel re-zeroes
// them at the end of every launch, so every graph replay starts from zero.
__device__ float g_sums[K_DIM * C_DIM];   // 16 KB
__device__ float g_counts[K_DIM];

// ---------------------------------------------------------------------------
// Fused kernel: blocks [0,256) reduce, rest stream the 1 GiB broadcast.
// Copy path: 32 KB per block, 8 batched LDG.128 -> 8 STG.128 (__stcs),
// MLP=8 to cover DRAM latency through wave transitions.
// ---------------------------------------------------------------------------
__global__ __launch_bounds__(256) void fused_kernel(
    const float* __restrict__ x, const float* __restrict__ oh,
    float4* __restrict__ out4)
{
    int bid = blockIdx.x;
    int tid = threadIdx.x;

    if (bid < RED_BLOCKS) {
        // ---- reduction path: 256 pixels per block ----
        __shared__ float ssum[K_DIM][C_DIM + 1];  // padded rows vs bank conflicts
        __shared__ float scnt[K_DIM];

        for (int i = tid; i < K_DIM * (C_DIM + 1); i += 256)
            (&ssum[0][0])[i] = 0.0f;
        if (tid < K_DIM) scnt[tid] = 0.0f;
        __syncthreads();

        int p = bid * 256 + tid;

        // Recover the one-hot label (coalesced scan over K).
        int label = 0;
        #pragma unroll 8
        for (int k = 0; k < K_DIM; k++) {
            if (__ldg(&oh[(size_t)k * P_DIM + p]) != 0.0f) label = k;
        }
        atomicAdd(&scnt[label], 1.0f);

        #pragma unroll 8
        for (int c = 0; c < C_DIM; c++) {
            atomicAdd(&ssum[label][c], __ldg(&x[(size_t)c * P_DIM + p]));
        }
        __syncthreads();

        // Flush block partials via global atomics (4096 spread addresses,
        // hidden under the DRAM-bound copy).
        for (int i = tid; i < K_DIM * C_DIM; i += 256) {
            atomicAdd(&g_sums[i], ssum[i >> 6][i & 63]);
        }
        if (tid < K_DIM) {
            atomicAdd(&g_counts[tid], scnt[tid]);
        }
    } else {
        // ---- broadcast path: one 32 KB chunk of one replica ----
        int b  = bid - RED_BLOCKS;
        int k  = b >> 9;                     // replica index (512 chunks/rep)
        int cb = b & (CHUNKS_PER_REP - 1);

        const float4* src = (const float4*)x + (size_t)cb * F4_PER_CHUNK;
        float4* dst = out4 + (size_t)k * N4_PER_REP + (size_t)cb * F4_PER_CHUNK;

        float4 v0 = __ldg(src + tid);
        float4 v1 = __ldg(src +  256 + tid);
        float4 v2 = __ldg(src +  512 + tid);
        float4 v3 = __ldg(src +  768 + tid);
        float4 v4 = __ldg(src + 1024 + tid);
        float4 v5 = __ldg(src + 1280 + tid);
        float4 v6 = __ldg(src + 1536 + tid);
        float4 v7 = __ldg(src + 1792 + tid);
        __stcs(dst + tid,        v0);
        __stcs(dst +  256 + tid, v1);
        __stcs(dst +  512 + tid, v2);
        __stcs(dst +  768 + tid, v3);
        __stcs(dst + 1024 + tid, v4);
        __stcs(dst + 1280 + tid, v5);
        __stcs(dst + 1536 + tid, v6);
        __stcs(dst + 1792 + tid, v7);
    }
}

// ---------------------------------------------------------------------------
// Means: one thread per (k,c); 16 KB of reads, one divide. Self-resets the
// accumulators for the next graph replay (block-exclusive k ranges).
// ---------------------------------------------------------------------------
__global__ __launch_bounds__(256) void means_kernel(float* __restrict__ out_means)
{
    int i = blockIdx.x * 256 + threadIdx.x;   // 0..4095
    int k = i >> 6;

    float s   = g_sums[i];
    float cnt = g_counts[k];
    float denom = cnt + (cnt == 0.0f ? 1.0f : 0.0f);
    out_means[i] = s / denom;

    __syncthreads();   // all reads of this block's g_counts range done

    g_sums[i] = 0.0f;
    if ((i & 63) == 0) g_counts[k] = 0.0f;   // k exclusive to this block
}

// ---------------------------------------------------------------------------
extern "C" void kernel_launch(void* const* d_in, const int* in_sizes, int n_in,
                              void* d_out, int out_size)
{
    const float* x  = (const float*)d_in[0];   // [1, 64, 256, 256]
    const float* oh = (const float*)d_in[1];   // [1, 64, 256, 256] one-hot
    float* out = (float*)d_out;

    // Output layout: input_r (K*C*H*W floats) then regional_means (K*C).
    float* out_means = out + (size_t)out_size - (size_t)(K_DIM * C_DIM);

    fused_kernel<<<RED_BLOCKS + COPY_BLOCKS, 256>>>(x, oh, (float4*)out);
    means_kernel<<<(K_DIM * C_DIM) / 256, 256>>>(out_means);
}

// round 12
// speedup vs baseline: 1.0247x; 1.0247x over previous
#include <cuda_runtime.h>
#include <cstddef>

#define C_DIM 64
#define K_DIM 64
#define P_DIM (256 * 256)        // H*W = 65536
#define RED_BLOCKS 256           // reduction blocks (256 pixels each)
#define CHUNKS_PER_REP 2048      // 8 KB chunks
#define COPY_BLOCKS (K_DIM * CHUNKS_PER_REP)        // 131072
#define N4_PER_REP (C_DIM * P_DIM / 4)              // 1,048,576 float4 per replica
#define F4_PER_CHUNK (N4_PER_REP / CHUNKS_PER_REP)  // 512 float4 = 8KB

// Global accumulators. Zero-initialized at load; the means kernel re-zeroes
// them at the end of every launch, so every graph replay starts from zero.
__device__ float g_sums[K_DIM * C_DIM];   // 16 KB
__device__ float g_counts[K_DIM];

// ---------------------------------------------------------------------------
// Fused kernel: blocks [0,256) reduce, rest stream the 1 GiB broadcast.
// Copy path: 8 KB per block (2 batched LDG.128 -> 2 STG.128 __stcs) —
// finer scheduling granularity to smooth wave transitions.
// ---------------------------------------------------------------------------
__global__ __launch_bounds__(256) void fused_kernel(
    const float* __restrict__ x, const float* __restrict__ oh,
    float4* __restrict__ out4)
{
    int bid = blockIdx.x;
    int tid = threadIdx.x;

    if (bid < RED_BLOCKS) {
        // ---- reduction path: 256 pixels per block ----
        __shared__ float ssum[K_DIM][C_DIM + 1];  // padded rows vs bank conflicts
        __shared__ float scnt[K_DIM];

        for (int i = tid; i < K_DIM * (C_DIM + 1); i += 256)
            (&ssum[0][0])[i] = 0.0f;
        if (tid < K_DIM) scnt[tid] = 0.0f;
        __syncthreads();

        int p = bid * 256 + tid;

        // Recover the one-hot label (coalesced scan over K).
        int label = 0;
        #pragma unroll 8
        for (int k = 0; k < K_DIM; k++) {
            if (__ldg(&oh[(size_t)k * P_DIM + p]) != 0.0f) label = k;
        }
        atomicAdd(&scnt[label], 1.0f);

        #pragma unroll 8
        for (int c = 0; c < C_DIM; c++) {
            atomicAdd(&ssum[label][c], __ldg(&x[(size_t)c * P_DIM + p]));
        }
        __syncthreads();

        // Flush block partials via global atomics (4096 spread addresses,
        // hidden under the DRAM-bound copy).
        for (int i = tid; i < K_DIM * C_DIM; i += 256) {
            float v = ssum[i >> 6][i & 63];
            if (v != 0.0f) atomicAdd(&g_sums[i], v);
        }
        if (tid < K_DIM) {
            float v = scnt[tid];
            if (v != 0.0f) atomicAdd(&g_counts[tid], v);
        }
    } else {
        // ---- broadcast path: one 8 KB chunk of one replica ----
        int b  = bid - RED_BLOCKS;
        int k  = b >> 11;                    // replica index (2048 chunks/rep)
        int cb = b & (CHUNKS_PER_REP - 1);

        const float4* src = (const float4*)x + (size_t)cb * F4_PER_CHUNK;
        float4* dst = out4 + (size_t)k * N4_PER_REP + (size_t)cb * F4_PER_CHUNK;

        float4 v0 = __ldg(src + tid);
        float4 v1 = __ldg(src + 256 + tid);
        __stcs(dst + tid,       v0);
        __stcs(dst + 256 + tid, v1);
    }
}

// ---------------------------------------------------------------------------
// Means: one thread per (k,c); 16 KB of reads, one divide. Self-resets the
// accumulators for the next graph replay (block-exclusive k ranges).
// ---------------------------------------------------------------------------
__global__ __launch_bounds__(256) void means_kernel(float* __restrict__ out_means)
{
    int i = blockIdx.x * 256 + threadIdx.x;   // 0..4095
    int k = i >> 6;

    float s   = g_sums[i];
    float cnt = g_counts[k];
    float denom = cnt + (cnt == 0.0f ? 1.0f : 0.0f);
    out_means[i] = s / denom;

    __syncthreads();   // all reads of this block's g_counts range done

    g_sums[i] = 0.0f;
    if ((i & 63) == 0) g_counts[k] = 0.0f;   // k exclusive to this block
}

// ---------------------------------------------------------------------------
extern "C" void kernel_launch(void* const* d_in, const int* in_sizes, int n_in,
                              void* d_out, int out_size)
{
    const float* x  = (const float*)d_in[0];   // [1, 64, 256, 256]
    const float* oh = (const float*)d_in[1];   // [1, 64, 256, 256] one-hot
    float* out = (float*)d_out;

    // Output layout: input_r (K*C*H*W floats) then regional_means (K*C).
    float* out_means = out + (size_t)out_size - (size_t)(K_DIM * C_DIM);

    fused_kernel<<<RED_BLOCKS + COPY_BLOCKS, 256>>>(x, oh, (float4*)out);
    means_kernel<<<(K_DIM * C_DIM) / 256, 256>>>(out_means);
}